// round 4
// baseline (speedup 1.0000x reference)
#include <cuda_runtime.h>

typedef unsigned long long ULL;
typedef unsigned int uint;

constexpr int B    = 512;
constexpr int T    = 2048;
constexpr int H    = 64;
constexpr int G    = 4 * H;    // 256 gates (i,f,g,o blocks of 64)
constexpr int NB   = 4;        // batch elements per block (2 f32x2 pairs)
constexpr int NBLK = B / NB;   // 128 blocks
constexpr int NGT  = 2 * G;    // 512 gate threads (2 k-halves per gate)
constexpr int NTHR = NGT + 64; // + 2 layer-2 warps = 576

__device__ __forceinline__ ULL pack2(float x, float y) {
    ULL r; asm("mov.b64 %0, {%1, %2};" : "=l"(r) : "f"(x), "f"(y)); return r;
}
__device__ __forceinline__ void unpack2(ULL v, float& x, float& y) {
    asm("mov.b64 {%0, %1}, %2;" : "=f"(x), "=f"(y) : "l"(v));
}
__device__ __forceinline__ ULL ffma2(ULL a, ULL b, ULL c) {
    ULL d; asm("fma.rn.f32x2 %0, %1, %2, %3;" : "=l"(d) : "l"(a), "l"(b), "l"(c)); return d;
}
__device__ __forceinline__ ULL fadd2(ULL a, ULL b) {
    ULL d; asm("add.rn.f32x2 %0, %1, %2;" : "=l"(d) : "l"(a), "l"(b)); return d;
}
__device__ __forceinline__ ULL shfl_xor_ull(ULL v, int m) {
    uint lo, hi;
    asm("mov.b64 {%0, %1}, %2;" : "=r"(lo), "=r"(hi) : "l"(v));
    lo = __shfl_xor_sync(0xffffffffu, lo, m);
    hi = __shfl_xor_sync(0xffffffffu, hi, m);
    ULL r; asm("mov.b64 %0, {%1, %2};" : "=l"(r) : "r"(lo), "r"(hi));
    return r;
}
__device__ __forceinline__ float fsigm(float x) {
    return __fdividef(1.f, 1.f + __expf(-x));
}
__device__ __forceinline__ float ftanh(float x) {
    return __fdividef(2.f, 1.f + __expf(-2.f * x)) - 1.f;
}

__global__ __launch_bounds__(NTHR, 1)
void lstm2_kernel(const float* __restrict__ x,
                  const float* __restrict__ Wih1,
                  const float* __restrict__ Whh1,
                  const float* __restrict__ bih1,
                  const float* __restrict__ bhh1,
                  const float* __restrict__ Wih2,
                  const float* __restrict__ Whh2,
                  const float* __restrict__ bih2,
                  const float* __restrict__ bhh2,
                  float* __restrict__ out)
{
    // x for this block's 4 batch rows, interleaved for 8B/16B vector reads
    __shared__ __align__(16) float xs[T][NB];
    // h1 state: unit j stored at h2[j&31][j>>5][*] so the two k-halves of a
    // warp read adjacent 16B segments (conflict-free single phase)
    __shared__ __align__(16) float h2s[32][2][NB];
    __shared__ __align__(16) float gs[G][NB];        // activated gates
    __shared__ __align__(16) float c1buf[2][H][NB];  // double-buffered c1 for layer 2

    const int tid = threadIdx.x;
    const int b0  = blockIdx.x * NB;

    // ---- one-time preload ----
    #pragma unroll
    for (int bl = 0; bl < NB; bl++)
        for (int t = tid; t < T; t += NTHR)
            xs[t][bl] = x[(b0 + bl) * T + t];
    for (int i = tid; i < 32 * 2 * NB; i += NTHR)
        (&h2s[0][0][0])[i] = 0.f;

    const bool is_gate = tid < NGT;

    // gate-thread persistent state: packed recurrent weights (one k-half)
    ULL ww[32];
    ULL wxp = 0, bp = 0;
    int g = 0, half = 0;
    float c1s0 = 0.f, c1s1 = 0.f, c1s2 = 0.f, c1s3 = 0.f;
    if (is_gate) {
        g    = tid >> 1;
        half = tid & 1;
        #pragma unroll
        for (int i = 0; i < 32; i++) {
            float w = Whh1[g * H + half * 32 + i];
            ww[i] = pack2(w, w);
        }
        if (!half) {
            float wi = Wih1[g];
            wxp = pack2(wi, wi);
            float bb = bih1[g] + bhh1[g];
            bp = pack2(bb, bb);
        }
    }

    // layer-2 thread state (tid in [512,576)): (bl, gate q, k-segment of 16)
    float w2[16];
    float whh2q = 0.f, b2q = 0.f, h2v = 0.f, c2 = 0.f;
    const int l = tid - NGT;
    int bl2 = 0, ks = 0;
    if (!is_gate) {
        bl2 = l >> 4;
        const int q = (l >> 2) & 3;
        ks = (l & 3) * 16;
        #pragma unroll
        for (int j = 0; j < 16; j++) w2[j] = Wih2[q * H + ks + j];
        whh2q = Whh2[q];
        b2q   = bih2[q] + bhh2[q];
    }
    __syncthreads();

    for (int t = 0; t <= T; t++) {
        // ---------- phase A: layer-1 gates (t) || layer-2 (t-1) ----------
        if (is_gate) {
            if (t < T) {
                ULL acc0 = 0, acc1 = 0;
                if (!half) {
                    ULL xp01 = *reinterpret_cast<const ULL*>(&xs[t][0]);
                    ULL xp23 = *reinterpret_cast<const ULL*>(&xs[t][2]);
                    acc0 = ffma2(wxp, xp01, bp);
                    acc1 = ffma2(wxp, xp23, bp);
                }
                #pragma unroll
                for (int i = 0; i < 32; i++) {
                    ulonglong2 hv =
                        *reinterpret_cast<const ulonglong2*>(&h2s[i][half][0]);
                    acc0 = ffma2(ww[i], hv.x, acc0);
                    acc1 = ffma2(ww[i], hv.y, acc1);
                }
                // exchange: even lane finalizes batches 0-1 (acc0),
                // odd lane finalizes batches 2-3 (acc1)
                ULL send = half ? acc0 : acc1;
                ULL recv = shfl_xor_ull(send, 1);
                ULL keep = half ? acc1 : acc0;
                ULL full = fadd2(keep, recv);
                float va, vb;
                unpack2(full, va, vb);
                if ((g >> 6) == 2) { va = ftanh(va); vb = ftanh(vb); }
                else               { va = fsigm(va); vb = fsigm(vb); }
                *reinterpret_cast<float2*>(&gs[g][half * 2]) =
                    make_float2(va, vb);
            }
        } else if (t > 0) {
            // layer 2 consumes c1 of step t-1 (pipelined one step behind)
            const float* cb = &c1buf[(t + 1) & 1][0][0];
            float s = 0.f;
            #pragma unroll
            for (int j = 0; j < 16; j++)
                s = fmaf(cb[(ks + j) * NB + bl2], w2[j], s);
            s += __shfl_xor_sync(0xffffffffu, s, 1);
            s += __shfl_xor_sync(0xffffffffu, s, 2);
            const float gate = s + b2q + h2v * whh2q;
            const int lane = l & 31;
            const int base = lane & 16;
            const float gi = __shfl_sync(0xffffffffu, gate, base + 0);
            const float gf = __shfl_sync(0xffffffffu, gate, base + 4);
            const float gg = __shfl_sync(0xffffffffu, gate, base + 8);
            const float go = __shfl_sync(0xffffffffu, gate, base + 12);
            c2  = fsigm(gf) * c2 + fsigm(gi) * ftanh(gg);
            h2v = fsigm(go) * ftanh(c2);
            if ((lane & 15) == 0)
                out[(b0 + bl2) * T + (t - 1)] = c2;
        }
        __syncthreads();
        // ---------- phase B: h1/c1 state update ----------
        if (tid < H && t < T) {
            const int j = tid;
            float4 gi4 = *reinterpret_cast<const float4*>(&gs[j][0]);
            float4 gf4 = *reinterpret_cast<const float4*>(&gs[H + j][0]);
            float4 gg4 = *reinterpret_cast<const float4*>(&gs[2 * H + j][0]);
            float4 go4 = *reinterpret_cast<const float4*>(&gs[3 * H + j][0]);
            float c0  = fmaf(gf4.x, c1s0, gi4.x * gg4.x);
            float c1_ = fmaf(gf4.y, c1s1, gi4.y * gg4.y);
            float cc  = fmaf(gf4.z, c1s2, gi4.z * gg4.z);
            float c3  = fmaf(gf4.w, c1s3, gi4.w * gg4.w);
            c1s0 = c0; c1s1 = c1_; c1s2 = cc; c1s3 = c3;
            float4 hn = make_float4(go4.x * ftanh(c0), go4.y * ftanh(c1_),
                                    go4.z * ftanh(cc), go4.w * ftanh(c3));
            *reinterpret_cast<float4*>(&h2s[j & 31][j >> 5][0]) = hn;
            *reinterpret_cast<float4*>(&c1buf[t & 1][j][0]) =
                make_float4(c0, c1_, cc, c3);
        }
        __syncthreads();
    }
}

extern "C" void kernel_launch(void* const* d_in, const int* in_sizes, int n_in,
                              void* d_out, int out_size) {
    (void)in_sizes; (void)n_in; (void)out_size;
    lstm2_kernel<<<NBLK, NTHR>>>(
        (const float*)d_in[0],  // x
        (const float*)d_in[1],  // Wih1
        (const float*)d_in[2],  // Whh1
        (const float*)d_in[3],  // bih1
        (const float*)d_in[4],  // bhh1
        (const float*)d_in[5],  // Wih2
        (const float*)d_in[6],  // Whh2
        (const float*)d_in[7],  // bih2
        (const float*)d_in[8],  // bhh2
        (float*)d_out);
}

// round 5
// speedup vs baseline: 1.0605x; 1.0605x over previous
#include <cuda_runtime.h>

typedef unsigned long long ULL;
typedef unsigned int uint;

constexpr int B    = 512;
constexpr int T    = 2048;
constexpr int H    = 64;
constexpr int G    = 4 * H;   // 256 gates (i,f,g,o blocks of 64)
constexpr int NB   = 4;       // batch elements per block (2 f32x2 pairs)
constexpr int NBLK = B / NB;  // 128 blocks
constexpr int NGT  = 256;     // gate threads: (j, q) -> lane = (j&7)*4 + q
constexpr int NTHR = NGT + 64;// + 2 layer-2 warps = 320

__device__ __forceinline__ ULL pack2(float x, float y) {
    ULL r; asm("mov.b64 %0, {%1, %2};" : "=l"(r) : "f"(x), "f"(y)); return r;
}
__device__ __forceinline__ void unpack2(ULL v, float& x, float& y) {
    asm("mov.b64 {%0, %1}, %2;" : "=f"(x), "=f"(y) : "l"(v));
}
__device__ __forceinline__ ULL ffma2(ULL a, ULL b, ULL c) {
    ULL d; asm("fma.rn.f32x2 %0, %1, %2, %3;" : "=l"(d) : "l"(a), "l"(b), "l"(c)); return d;
}
__device__ __forceinline__ float fsigm(float x) {
    return __fdividef(1.f, 1.f + __expf(-x));
}
__device__ __forceinline__ float ftanh(float x) {
    return __fdividef(2.f, 1.f + __expf(-2.f * x)) - 1.f;
}

__global__ __launch_bounds__(NTHR, 1)
void lstm2_kernel(const float* __restrict__ x,
                  const float* __restrict__ Wih1,
                  const float* __restrict__ Whh1,
                  const float* __restrict__ bih1,
                  const float* __restrict__ bhh1,
                  const float* __restrict__ Wih2,
                  const float* __restrict__ Whh2,
                  const float* __restrict__ bih2,
                  const float* __restrict__ bhh2,
                  float* __restrict__ out)
{
    __shared__ __align__(16) float xs[T][NB];        // 32KB input stage
    __shared__ __align__(16) float h2s[2][H][NB];    // double-buffered h1
    __shared__ __align__(16) float c1buf[2][H][NB];  // double-buffered c1 (layer 2)

    const int tid = threadIdx.x;
    const int b0  = blockIdx.x * NB;

    // ---- one-time preload ----
    #pragma unroll
    for (int bl = 0; bl < NB; bl++)
        for (int t = tid; t < T; t += NTHR)
            xs[t][bl] = x[(b0 + bl) * T + t];
    for (int i = tid; i < 2 * H * NB; i += NTHR)
        (&h2s[0][0][0])[i] = 0.f;

    const bool is_gate = tid < NGT;

    // gate thread mapping: q = lane&3 (gate: 0=i,1=f,2=g,3=o), j = tid>>2 (unit)
    ULL ww[H];
    ULL wxp = 0, bp = 0;
    int q = 0;
    float c1s = 0.f;
    bool isg = false;
    if (is_gate) {
        q = tid & 3;
        const int j = tid >> 2;
        const int g = q * H + j;      // torch gate-row order i,f,g,o
        isg = (q == 2);
        #pragma unroll
        for (int k = 0; k < H; k++) {
            float w = Whh1[g * H + k];
            ww[k] = pack2(w, w);
        }
        float wi = Wih1[g];
        wxp = pack2(wi, wi);
        float bb = bih1[g] + bhh1[g];
        bp = pack2(bb, bb);
    }

    // layer-2 thread state (tid in [256,320)): (bl, gate qq, k-segment of 16)
    float w2[16];
    float whh2q = 0.f, b2q = 0.f, h2v = 0.f, c2 = 0.f;
    const int l = tid - NGT;
    int bl2 = 0, ks = 0;
    if (!is_gate) {
        bl2 = l >> 4;
        const int qq = (l >> 2) & 3;
        ks = (l & 3) * 16;
        #pragma unroll
        for (int j = 0; j < 16; j++) w2[j] = Wih2[qq * H + ks + j];
        whh2q = Whh2[qq];
        b2q   = bih2[qq] + bhh2[qq];
    }
    __syncthreads();

    for (int t = 0; t <= T; t++) {
        const int wb = t & 1;       // write buffer this step
        const int rb = wb ^ 1;      // read buffer (prev step's h)
        if (is_gate) {
            if (t < T) {
                ULL xp01 = *reinterpret_cast<const ULL*>(&xs[t][0]);
                ULL xp23 = *reinterpret_cast<const ULL*>(&xs[t][2]);
                ULL acc0 = ffma2(wxp, xp01, bp);   // batches 0,1
                ULL acc1 = ffma2(wxp, xp23, bp);   // batches 2,3
                #pragma unroll
                for (int k = 0; k < H; k++) {
                    ulonglong2 hv =
                        *reinterpret_cast<const ulonglong2*>(&h2s[rb][k][0]);
                    acc0 = ffma2(ww[k], hv.x, acc0);
                    acc1 = ffma2(ww[k], hv.y, acc1);
                }
                float v0, v1, v2, v3;
                unpack2(acc0, v0, v1);
                unpack2(acc1, v2, v3);
                // branchless activation: tanh(x) = 2*sigmoid(2x)-1
                {
                    float s0 = fsigm(isg ? 2.f * v0 : v0);
                    float s1 = fsigm(isg ? 2.f * v1 : v1);
                    float s2 = fsigm(isg ? 2.f * v2 : v2);
                    float s3 = fsigm(isg ? 2.f * v3 : v3);
                    v0 = isg ? 2.f * s0 - 1.f : s0;
                    v1 = isg ? 2.f * s1 - 1.f : s1;
                    v2 = isg ? 2.f * s2 - 1.f : s2;
                    v3 = isg ? 2.f * s3 - 1.f : s3;
                }
                // 4x4 quad transpose: lane q ends with v[g] = gate g, batch q
                {
                    float a_ = ((q & 1) == 0) ? v1 : v0;
                    float b_ = ((q & 1) == 0) ? v3 : v2;
                    a_ = __shfl_xor_sync(0xffffffffu, a_, 1);
                    b_ = __shfl_xor_sync(0xffffffffu, b_, 1);
                    if ((q & 1) == 0) { v1 = a_; v3 = b_; }
                    else              { v0 = a_; v2 = b_; }
                    float c_ = ((q & 2) == 0) ? v2 : v0;
                    float d_ = ((q & 2) == 0) ? v3 : v1;
                    c_ = __shfl_xor_sync(0xffffffffu, c_, 2);
                    d_ = __shfl_xor_sync(0xffffffffu, d_, 2);
                    if ((q & 2) == 0) { v2 = c_; v3 = d_; }
                    else              { v0 = c_; v1 = d_; }
                }
                // lane q updates (unit j, batch q): v0=i v1=f v2=tanh(g) v3=o
                const int j = tid >> 2;
                c1s = fmaf(v1, c1s, v0 * v2);
                float hn = v3 * ftanh(c1s);
                h2s[wb][j][q]   = hn;
                c1buf[wb][j][q] = c1s;
            }
        } else if (t > 0) {
            // layer 2 consumes c1 of step t-1 (one step behind)
            const float* cb = &c1buf[(t + 1) & 1][0][0];
            float s = 0.f;
            #pragma unroll
            for (int j = 0; j < 16; j++)
                s = fmaf(cb[(ks + j) * NB + bl2], w2[j], s);
            s += __shfl_xor_sync(0xffffffffu, s, 1);
            s += __shfl_xor_sync(0xffffffffu, s, 2);
            const float gate = s + b2q + h2v * whh2q;
            const int lane = l & 31;
            const int base = lane & 16;
            const float gi = __shfl_sync(0xffffffffu, gate, base + 0);
            const float gf = __shfl_sync(0xffffffffu, gate, base + 4);
            const float gg = __shfl_sync(0xffffffffu, gate, base + 8);
            const float go = __shfl_sync(0xffffffffu, gate, base + 12);
            c2  = fsigm(gf) * c2 + fsigm(gi) * ftanh(gg);
            h2v = fsigm(go) * ftanh(c2);
            if ((lane & 15) == 0)
                out[(b0 + bl2) * T + (t - 1)] = c2;
        }
        __syncthreads();  // single barrier per step
    }
}

extern "C" void kernel_launch(void* const* d_in, const int* in_sizes, int n_in,
                              void* d_out, int out_size) {
    (void)in_sizes; (void)n_in; (void)out_size;
    lstm2_kernel<<<NBLK, NTHR>>>(
        (const float*)d_in[0],  // x
        (const float*)d_in[1],  // Wih1
        (const float*)d_in[2],  // Whh1
        (const float*)d_in[3],  // bih1
        (const float*)d_in[4],  // bhh1
        (const float*)d_in[5],  // Wih2
        (const float*)d_in[6],  // Whh2
        (const float*)d_in[7],  // bih2
        (const float*)d_in[8],  // bhh2
        (float*)d_out);
}